// round 4
// baseline (speedup 1.0000x reference)
#include <cuda_runtime.h>
#include <math.h>

#define BB 512
#define HH 1024
#define SS 1024
#define DD 128
#define KK 32
#define GG 4           // batches per frontend block
#define TA 256
#define NA (BB / GG)   // 128 frontend blocks

// scratch (no allocations allowed)
__device__ float g_gate[BB];
__device__ float g_value[BB * DD];
__device__ float g_topw[BB * KK];
__device__ int   g_topi[BB * KK];

// shared memory layout (float offsets)
#define OFF_Q      0        // 512:  q[4][128]
#define OFF_LOGIT  512      // 4096: logits[4][1024]
#define OFF_KEY    4608     // 8192: key tile [1024 s][8 d], chunk-swizzled
#define OFF_PART   4608     // 4096: per-warp GEMM partials (aliases KEY)
#define OFF_TOPW   12800    // 128
#define OFF_TOPI   12928    // 128
#define OFF_READ   13056    // 512
#define OFF_MISC   13568    // 32
#define SMEM_FLOATS 13600
#define SMEM_BYTES (SMEM_FLOATS * 4)

// ---- one-time stream/event resources (host-side, created at load) ----
struct AmtRes {
    cudaStream_t s2;
    cudaEvent_t e0, e1;
    AmtRes() {
        cudaStreamCreateWithFlags(&s2, cudaStreamNonBlocking);
        cudaEventCreateWithFlags(&e0, cudaEventDisableTiming);
        cudaEventCreateWithFlags(&e1, cudaEventDisableTiming);
    }
};
static AmtRes g_res;

__global__ void __launch_bounds__(TA)
amt_front(const float* __restrict__ latent,
          const float* __restrict__ memory,
          const float* __restrict__ rqw,  const float* __restrict__ rqb,
          const float* __restrict__ mkey,
          const float* __restrict__ wgw,  const float* __restrict__ wgb,
          const float* __restrict__ dmw,  const float* __restrict__ dmb,
          const float* __restrict__ phw,  const float* __restrict__ phb,
          const float* __restrict__ wvw,  const float* __restrict__ wvb,
          float* __restrict__ out)
{
    extern __shared__ float sm[];
    const int t    = threadIdx.x;
    const int lane = t & 31;
    const int w    = t >> 5;
    const int b0   = blockIdx.x * GG;

    float* out_read = out;                                           // [B][D]
    float* out_wts  = out + (size_t)BB * DD + (size_t)BB * SS * DD;  // [B][S]

    // ---- Phase 0: zero this block's weights rows ----
    {
        float4* p = (float4*)(out_wts + (size_t)b0 * SS);
        #pragma unroll
        for (int i = t; i < GG * SS / 4; i += TA)
            p[i] = make_float4(0.f, 0.f, 0.f, 0.f);
    }

    // ---- Phase 1: latent-side partial dots; warp w: g = w&3, half = w>>2 ----
    {
        const int g = w & 3, half = w >> 2;
        const float* lat = latent + (size_t)(b0 + g) * HH + half * 512;
        const int off = half * 512;
        float gl = 0.f, dl = 0.f, pl = 0.f;
        #pragma unroll 4
        for (int j = 0; j < 16; j++) {
            int h = j * 32 + lane;
            float lv = lat[h];
            gl += lv * wgw[off + h];
            dl += lv * dmw[off + h];
            pl += lv * phw[off + h];
        }
        #pragma unroll
        for (int o = 16; o > 0; o >>= 1) {
            gl += __shfl_down_sync(0xffffffffu, gl, o);
            dl += __shfl_down_sync(0xffffffffu, dl, o);
            pl += __shfl_down_sync(0xffffffffu, pl, o);
        }
        if (lane == 0) {
            sm[OFF_MISC + g * 8 + half * 4 + 0] = gl;
            sm[OFF_MISC + g * 8 + half * 4 + 1] = dl;
            sm[OFF_MISC + g * 8 + half * 4 + 2] = pl;
        }
    }

    // ---- latent register tile: warp w owns h in [w*128, w*128+128) ----
    float latreg[GG][4];
    {
        const int hb = w * 128;
        #pragma unroll
        for (int g = 0; g < GG; g++)
            #pragma unroll
            for (int k = 0; k < 4; k++)
                latreg[g][k] = latent[(size_t)(b0 + g) * HH + hb + k * 32 + lane];
    }

    // ---- Phase 2: query GEMM ----
    {
        const float4* W4 = (const float4*)rqw;
        float4 acc[GG];
        #pragma unroll
        for (int g = 0; g < GG; g++) acc[g] = make_float4(0.f, 0.f, 0.f, 0.f);
        const int hb = w * 128;
        #pragma unroll
        for (int k = 0; k < 4; k++) {
            #pragma unroll 8
            for (int i = 0; i < 32; i++) {
                float4 wv = W4[(size_t)(hb + k * 32 + i) * 32 + lane];
                #pragma unroll
                for (int g = 0; g < GG; g++) {
                    float a = __shfl_sync(0xffffffffu, latreg[g][k], i);
                    acc[g].x += a * wv.x; acc[g].y += a * wv.y;
                    acc[g].z += a * wv.z; acc[g].w += a * wv.w;
                }
            }
        }
        #pragma unroll
        for (int g = 0; g < GG; g++)
            *(float4*)&sm[OFF_PART + (w * GG + g) * DD + lane * 4] = acc[g];
    }
    __syncthreads();
    {   // reduce partials -> q
        const int d  = t & 127;
        const int g0 = t >> 7;
        #pragma unroll
        for (int j = 0; j < 2; j++) {
            int g = g0 + j * 2;
            float s = rqb[d];
            #pragma unroll
            for (int ww = 0; ww < 8; ww++) s += sm[OFF_PART + (ww * GG + g) * DD + d];
            sm[OFF_Q + g * DD + d] = s;
        }
    }
    __syncthreads();

    // ---- Phase 3: value GEMM ----
    {
        const float4* W4 = (const float4*)wvw;
        float4 acc[GG];
        #pragma unroll
        for (int g = 0; g < GG; g++) acc[g] = make_float4(0.f, 0.f, 0.f, 0.f);
        const int hb = w * 128;
        #pragma unroll
        for (int k = 0; k < 4; k++) {
            #pragma unroll 8
            for (int i = 0; i < 32; i++) {
                float4 wv = W4[(size_t)(hb + k * 32 + i) * 32 + lane];
                #pragma unroll
                for (int g = 0; g < GG; g++) {
                    float a = __shfl_sync(0xffffffffu, latreg[g][k], i);
                    acc[g].x += a * wv.x; acc[g].y += a * wv.y;
                    acc[g].z += a * wv.z; acc[g].w += a * wv.w;
                }
            }
        }
        #pragma unroll
        for (int g = 0; g < GG; g++)
            *(float4*)&sm[OFF_PART + (w * GG + g) * DD + lane * 4] = acc[g];
    }
    __syncthreads();
    {   // reduce partials -> g_value
        const int d  = t & 127;
        const int g0 = t >> 7;
        #pragma unroll
        for (int j = 0; j < 2; j++) {
            int g = g0 + j * 2;
            float s = wvb[d];
            #pragma unroll
            for (int ww = 0; ww < 8; ww++) s += sm[OFF_PART + (ww * GG + g) * DD + d];
            g_value[(size_t)(b0 + g) * DD + d] = s;
        }
    }

    // ---- Phase 4: logits[g][s] = q[g].mkey[s], 16 chunks of 8 d ----
    float lac[4][GG];
    #pragma unroll
    for (int u = 0; u < 4; u++)
        #pragma unroll
        for (int g = 0; g < GG; g++) lac[u][g] = 0.f;

    const float4* K4 = (const float4*)mkey;
    for (int dc = 0; dc < 16; dc++) {
        __syncthreads();
        #pragma unroll
        for (int p = t; p < SS * 2; p += TA) {
            int s = p >> 1;
            int j = p & 1;
            float4 kv = K4[(size_t)s * 32 + dc * 2 + j];
            int c = s * 2 + (j ^ ((s >> 2) & 1));
            *(float4*)&sm[OFF_KEY + c * 4] = kv;
        }
        __syncthreads();
        #pragma unroll
        for (int j = 0; j < 2; j++) {
            float4 q4[GG];
            #pragma unroll
            for (int g = 0; g < GG; g++)
                q4[g] = *(const float4*)&sm[OFF_Q + g * DD + dc * 8 + j * 4];
            #pragma unroll
            for (int u = 0; u < 4; u++) {
                int s = w * 128 + u * 32 + lane;
                int c = s * 2 + (j ^ ((s >> 2) & 1));
                float4 k4 = *(const float4*)&sm[OFF_KEY + c * 4];
                #pragma unroll
                for (int g = 0; g < GG; g++)
                    lac[u][g] += k4.x * q4[g].x + k4.y * q4[g].y
                               + k4.z * q4[g].z + k4.w * q4[g].w;
            }
        }
    }
    #pragma unroll
    for (int u = 0; u < 4; u++) {
        int s = w * 128 + u * 32 + lane;
        #pragma unroll
        for (int g = 0; g < GG; g++)
            sm[OFF_LOGIT + g * SS + s] = lac[u][g];
    }
    __syncthreads();

    // ---- Phase 5: top-32 + renormalized weights (warps 0..3, g = w) ----
    if (w < GG) {
        const int g = w;
        float* lrow = &sm[OFF_LOGIT + g * SS];
        float lmax = -INFINITY; int lidx = 0x7fffffff;
        #pragma unroll 4
        for (int j = 0; j < 32; j++) {
            float v = lrow[j * 32 + lane];
            if (v > lmax) { lmax = v; lidx = j * 32 + lane; }
        }
        float m0 = 0.f, myv = 0.f; int myi = 0;
        for (int k = 0; k < KK; k++) {
            float bv = lmax; int bi = lidx;
            #pragma unroll
            for (int o = 16; o > 0; o >>= 1) {
                float ov = __shfl_down_sync(0xffffffffu, bv, o);
                int   oi = __shfl_down_sync(0xffffffffu, bi, o);
                if (ov > bv || (ov == bv && oi < bi)) { bv = ov; bi = oi; }
            }
            bv = __shfl_sync(0xffffffffu, bv, 0);
            bi = __shfl_sync(0xffffffffu, bi, 0);
            if (k == 0) m0 = bv;
            if (lane == k) { myv = bv; myi = bi; }
            if ((bi & 31) == lane) {
                lrow[bi] = -INFINITY;
                lmax = -INFINITY; lidx = 0x7fffffff;
                #pragma unroll 4
                for (int j = 0; j < 32; j++) {
                    float v = lrow[j * 32 + lane];
                    if (v > lmax) { lmax = v; lidx = j * 32 + lane; }
                }
            }
        }
        float e = expf(myv - m0);
        float sum = e;
        #pragma unroll
        for (int o = 16; o > 0; o >>= 1) sum += __shfl_xor_sync(0xffffffffu, sum, o);
        float wgt = e / sum;
        sm[OFF_TOPW + g * KK + lane] = wgt;
        ((int*)sm)[OFF_TOPI + g * KK + lane] = myi;
        out_wts[(size_t)(b0 + g) * SS + myi] = wgt;
        g_topw[(size_t)(b0 + g) * KK + lane] = wgt;
        g_topi[(size_t)(b0 + g) * KK + lane] = myi;
    }
    __syncthreads();

    // ---- Phase 6: read[g][d] = sum_k w_k * memory[b][idx_k][d] ----
    {
        const int d  = t & 127;
        const int g0 = t >> 7;
        #pragma unroll
        for (int j = 0; j < 2; j++) {
            int g = g0 + j * 2;
            const float* mrow = memory + (size_t)(b0 + g) * SS * DD;
            float accr = 0.f;
            #pragma unroll 8
            for (int k = 0; k < KK; k++) {
                float wk = sm[OFF_TOPW + g * KK + k];
                int   ik = ((int*)sm)[OFF_TOPI + g * KK + k];
                accr += wk * mrow[(size_t)ik * DD + d];
            }
            sm[OFF_READ + g * DD + d] = accr;
            out_read[(size_t)(b0 + g) * DD + d] = accr;
        }
    }
    __syncthreads();

    // ---- Phase 7: gate (warps 0..3, g = w) ----
    if (w < GG) {
        const int g = w;
        float gr = 0.f, dr = 0.f;
        #pragma unroll
        for (int i = 0; i < 4; i++) {
            float rv = sm[OFF_READ + g * DD + lane * 4 + i];
            gr += rv * wgw[HH + lane * 4 + i];
            dr += rv * dmw[HH + lane * 4 + i];
        }
        #pragma unroll
        for (int o = 16; o > 0; o >>= 1) {
            gr += __shfl_down_sync(0xffffffffu, gr, o);
            dr += __shfl_down_sync(0xffffffffu, dr, o);
        }
        if (lane == 0) {
            float gl = sm[OFF_MISC + g * 8 + 0] + sm[OFF_MISC + g * 8 + 4];
            float dl = sm[OFF_MISC + g * 8 + 1] + sm[OFF_MISC + g * 8 + 5];
            float pl = sm[OFF_MISC + g * 8 + 2] + sm[OFF_MISC + g * 8 + 6];
            float gate = 1.f / (1.f + expf(-(gl + gr + wgb[0])));
            float dmd  = tanhf(dl + dr + dmb[0]);
            gate = gate * (0.75f + 0.25f * (dmd + 1.f));
            gate = fminf(fmaxf(gate, 0.f), 1.f);
            gate *= 0.5f * (1.f + cosf(pl + phb[0]));
            g_gate[b0 + g] = gate;
        }
    }
}

// ---- fixup: rewrite only the B*K modified rows (4 rows per warp) ----
__global__ void __launch_bounds__(256)
amt_fixup(const float* __restrict__ memory, float* __restrict__ out)
{
    const int lane = threadIdx.x & 31, wrp = threadIdx.x >> 5;
    const int W  = blockIdx.x * 8 + wrp;   // 0..4095
    const int r0 = W * 4;
    const int b  = r0 >> 5;
    const int k0 = r0 & 31;

    float gate = g_gate[b];
    const float4* v4 = (const float4*)g_value + (size_t)b * 32;
    float4 v = v4[lane];

    int idx[4]; float gw[4]; float4 m[4];
    const float4* m4 = (const float4*)memory;
    #pragma unroll
    for (int j = 0; j < 4; j++) {
        idx[j] = g_topi[b * KK + k0 + j];
        gw[j]  = gate * g_topw[b * KK + k0 + j];
    }
    #pragma unroll
    for (int j = 0; j < 4; j++)
        m[j] = m4[((size_t)b * SS + idx[j]) * 32 + lane];

    float4* o4 = (float4*)(out + (size_t)BB * DD);
    #pragma unroll
    for (int j = 0; j < 4; j++) {
        float4 r = m[j];
        r.x += gw[j] * (v.x - r.x);
        r.y += gw[j] * (v.y - r.y);
        r.z += gw[j] * (v.z - r.z);
        r.w += gw[j] * (v.w - r.w);
        o4[((size_t)b * SS + idx[j]) * 32 + lane] = r;
    }
}

extern "C" void kernel_launch(void* const* d_in, const int* in_sizes, int n_in,
                              void* d_out, int out_size)
{
    const float* latent = (const float*)d_in[0];
    const float* memory = (const float*)d_in[1];
    const float* rqw    = (const float*)d_in[2];
    const float* rqb    = (const float*)d_in[3];
    const float* mkey   = (const float*)d_in[4];
    const float* wgw    = (const float*)d_in[5];
    const float* wgb    = (const float*)d_in[6];
    const float* dmw    = (const float*)d_in[7];
    const float* dmb    = (const float*)d_in[8];
    const float* phw    = (const float*)d_in[9];
    const float* phb    = (const float*)d_in[10];
    const float* wvw    = (const float*)d_in[11];
    const float* wvb    = (const float*)d_in[12];
    float* out = (float*)d_out;

    cudaFuncSetAttribute(amt_front, cudaFuncAttributeMaxDynamicSharedMemorySize, SMEM_BYTES);

    // Fork: CE bulk copy memory -> out.new_memory on side stream, concurrent
    // with the frontend kernel on the main stream. Join before fixup.
    cudaEventRecord(g_res.e0, 0);
    cudaStreamWaitEvent(g_res.s2, g_res.e0, 0);
    cudaMemcpyAsync(out + (size_t)BB * DD, memory,
                    (size_t)BB * SS * DD * sizeof(float),
                    cudaMemcpyDeviceToDevice, g_res.s2);
    cudaEventRecord(g_res.e1, g_res.s2);

    amt_front<<<NA, TA, SMEM_BYTES>>>(latent, memory, rqw, rqb, mkey,
                                      wgw, wgb, dmw, dmb, phw, phb,
                                      wvw, wvb, out);

    cudaStreamWaitEvent(0, g_res.e1, 0);
    amt_fixup<<<512, 256>>>(memory, out);
}

// round 5
// speedup vs baseline: 1.4040x; 1.4040x over previous
#include <cuda_runtime.h>
#include <math.h>

#define BB 512
#define HH 1024
#define SS 1024
#define DD 128
#define KK 32
#define GG 4           // batches per frontend block
#define TA 256
#define NA (BB / GG)   // 128 frontend blocks
#define NCPY 8192      // copy blocks: 8192 * 256 threads * 8 float4 = 256MB

// scratch (no allocations allowed)
__device__ float g_gate[BB];
__device__ float g_value[BB * DD];
__device__ float g_topw[BB * KK];
__device__ int   g_topi[BB * KK];

// shared memory layout (float offsets)
#define OFF_Q      0        // 512:  q[4][128]
#define OFF_LOGIT  512      // 4096: logits[4][1024]
#define OFF_KEY    4608     // 8192: key tile [1024 s][8 d], chunk-swizzled
#define OFF_PART   4608     // 4096: per-warp GEMM partials (aliases KEY)
#define OFF_TOPW   12800    // 128
#define OFF_TOPI   12928    // 128
#define OFF_READ   13056    // 512
#define OFF_MISC   13568    // 32
#define SMEM_FLOATS 13600
#define SMEM_BYTES (SMEM_FLOATS * 4)

// ---- one-time stream/event resources (host-side, created at load) ----
struct AmtRes {
    cudaStream_t s2;
    cudaEvent_t e0, e1;
    AmtRes() {
        int lo, hi;
        cudaDeviceGetStreamPriorityRange(&lo, &hi);
        cudaStreamCreateWithPriority(&s2, cudaStreamNonBlocking, lo); // low prio: copy backfills
        cudaEventCreateWithFlags(&e0, cudaEventDisableTiming);
        cudaEventCreateWithFlags(&e1, cudaEventDisableTiming);
    }
};
static AmtRes g_res;

// ---- SM streaming copy: memory -> out.new_memory (256 MB) ----
__global__ void __launch_bounds__(256)
amt_copy(const float* __restrict__ memory, float* __restrict__ out)
{
    const int t = threadIdx.x;
    const size_t base = (size_t)blockIdx.x * 2048 + t;
    const float4* s4 = (const float4*)memory;
    float4* o4 = (float4*)(out + (size_t)BB * DD);
    float4 v[8];
    #pragma unroll
    for (int k = 0; k < 8; k++) v[k] = __ldcs(&s4[base + (size_t)k * 256]);
    #pragma unroll
    for (int k = 0; k < 8; k++) __stcs(&o4[base + (size_t)k * 256], v[k]);
}

__global__ void __launch_bounds__(TA)
amt_front(const float* __restrict__ latent,
          const float* __restrict__ memory,
          const float* __restrict__ rqw,  const float* __restrict__ rqb,
          const float* __restrict__ mkey,
          const float* __restrict__ wgw,  const float* __restrict__ wgb,
          const float* __restrict__ dmw,  const float* __restrict__ dmb,
          const float* __restrict__ phw,  const float* __restrict__ phb,
          const float* __restrict__ wvw,  const float* __restrict__ wvb,
          float* __restrict__ out)
{
    extern __shared__ float sm[];
    const int t    = threadIdx.x;
    const int lane = t & 31;
    const int w    = t >> 5;
    const int b0   = blockIdx.x * GG;

    float* out_read = out;                                           // [B][D]
    float* out_wts  = out + (size_t)BB * DD + (size_t)BB * SS * DD;  // [B][S]

    // ---- Phase 0: zero this block's weights rows ----
    {
        float4* p = (float4*)(out_wts + (size_t)b0 * SS);
        #pragma unroll
        for (int i = t; i < GG * SS / 4; i += TA)
            p[i] = make_float4(0.f, 0.f, 0.f, 0.f);
    }

    // ---- Phase 1: latent-side partial dots; warp w: g = w&3, half = w>>2 ----
    {
        const int g = w & 3, half = w >> 2;
        const float* lat = latent + (size_t)(b0 + g) * HH + half * 512;
        const int off = half * 512;
        float gl = 0.f, dl = 0.f, pl = 0.f;
        #pragma unroll 4
        for (int j = 0; j < 16; j++) {
            int h = j * 32 + lane;
            float lv = lat[h];
            gl += lv * wgw[off + h];
            dl += lv * dmw[off + h];
            pl += lv * phw[off + h];
        }
        #pragma unroll
        for (int o = 16; o > 0; o >>= 1) {
            gl += __shfl_down_sync(0xffffffffu, gl, o);
            dl += __shfl_down_sync(0xffffffffu, dl, o);
            pl += __shfl_down_sync(0xffffffffu, pl, o);
        }
        if (lane == 0) {
            sm[OFF_MISC + g * 8 + half * 4 + 0] = gl;
            sm[OFF_MISC + g * 8 + half * 4 + 1] = dl;
            sm[OFF_MISC + g * 8 + half * 4 + 2] = pl;
        }
    }

    // ---- latent register tile: warp w owns h in [w*128, w*128+128) ----
    float latreg[GG][4];
    {
        const int hb = w * 128;
        #pragma unroll
        for (int g = 0; g < GG; g++)
            #pragma unroll
            for (int k = 0; k < 4; k++)
                latreg[g][k] = latent[(size_t)(b0 + g) * HH + hb + k * 32 + lane];
    }

    // ---- Phase 2: query GEMM ----
    {
        const float4* W4 = (const float4*)rqw;
        float4 acc[GG];
        #pragma unroll
        for (int g = 0; g < GG; g++) acc[g] = make_float4(0.f, 0.f, 0.f, 0.f);
        const int hb = w * 128;
        #pragma unroll
        for (int k = 0; k < 4; k++) {
            #pragma unroll 8
            for (int i = 0; i < 32; i++) {
                float4 wv = W4[(size_t)(hb + k * 32 + i) * 32 + lane];
                #pragma unroll
                for (int g = 0; g < GG; g++) {
                    float a = __shfl_sync(0xffffffffu, latreg[g][k], i);
                    acc[g].x += a * wv.x; acc[g].y += a * wv.y;
                    acc[g].z += a * wv.z; acc[g].w += a * wv.w;
                }
            }
        }
        #pragma unroll
        for (int g = 0; g < GG; g++)
            *(float4*)&sm[OFF_PART + (w * GG + g) * DD + lane * 4] = acc[g];
    }
    __syncthreads();
    {   // reduce partials -> q
        const int d  = t & 127;
        const int g0 = t >> 7;
        #pragma unroll
        for (int j = 0; j < 2; j++) {
            int g = g0 + j * 2;
            float s = rqb[d];
            #pragma unroll
            for (int ww = 0; ww < 8; ww++) s += sm[OFF_PART + (ww * GG + g) * DD + d];
            sm[OFF_Q + g * DD + d] = s;
        }
    }
    __syncthreads();

    // ---- Phase 3: value GEMM ----
    {
        const float4* W4 = (const float4*)wvw;
        float4 acc[GG];
        #pragma unroll
        for (int g = 0; g < GG; g++) acc[g] = make_float4(0.f, 0.f, 0.f, 0.f);
        const int hb = w * 128;
        #pragma unroll
        for (int k = 0; k < 4; k++) {
            #pragma unroll 8
            for (int i = 0; i < 32; i++) {
                float4 wv = W4[(size_t)(hb + k * 32 + i) * 32 + lane];
                #pragma unroll
                for (int g = 0; g < GG; g++) {
                    float a = __shfl_sync(0xffffffffu, latreg[g][k], i);
                    acc[g].x += a * wv.x; acc[g].y += a * wv.y;
                    acc[g].z += a * wv.z; acc[g].w += a * wv.w;
                }
            }
        }
        #pragma unroll
        for (int g = 0; g < GG; g++)
            *(float4*)&sm[OFF_PART + (w * GG + g) * DD + lane * 4] = acc[g];
    }
    __syncthreads();
    {   // reduce partials -> g_value
        const int d  = t & 127;
        const int g0 = t >> 7;
        #pragma unroll
        for (int j = 0; j < 2; j++) {
            int g = g0 + j * 2;
            float s = wvb[d];
            #pragma unroll
            for (int ww = 0; ww < 8; ww++) s += sm[OFF_PART + (ww * GG + g) * DD + d];
            g_value[(size_t)(b0 + g) * DD + d] = s;
        }
    }

    // ---- Phase 4: logits[g][s] = q[g].mkey[s], 16 chunks of 8 d ----
    float lac[4][GG];
    #pragma unroll
    for (int u = 0; u < 4; u++)
        #pragma unroll
        for (int g = 0; g < GG; g++) lac[u][g] = 0.f;

    const float4* K4 = (const float4*)mkey;
    for (int dc = 0; dc < 16; dc++) {
        __syncthreads();
        #pragma unroll
        for (int p = t; p < SS * 2; p += TA) {
            int s = p >> 1;
            int j = p & 1;
            float4 kv = K4[(size_t)s * 32 + dc * 2 + j];
            int c = s * 2 + (j ^ ((s >> 2) & 1));
            *(float4*)&sm[OFF_KEY + c * 4] = kv;
        }
        __syncthreads();
        #pragma unroll
        for (int j = 0; j < 2; j++) {
            float4 q4[GG];
            #pragma unroll
            for (int g = 0; g < GG; g++)
                q4[g] = *(const float4*)&sm[OFF_Q + g * DD + dc * 8 + j * 4];
            #pragma unroll
            for (int u = 0; u < 4; u++) {
                int s = w * 128 + u * 32 + lane;
                int c = s * 2 + (j ^ ((s >> 2) & 1));
                float4 k4 = *(const float4*)&sm[OFF_KEY + c * 4];
                #pragma unroll
                for (int g = 0; g < GG; g++)
                    lac[u][g] += k4.x * q4[g].x + k4.y * q4[g].y
                               + k4.z * q4[g].z + k4.w * q4[g].w;
            }
        }
    }
    #pragma unroll
    for (int u = 0; u < 4; u++) {
        int s = w * 128 + u * 32 + lane;
        #pragma unroll
        for (int g = 0; g < GG; g++)
            sm[OFF_LOGIT + g * SS + s] = lac[u][g];
    }
    __syncthreads();

    // ---- Phase 5: top-32 + renormalized weights (warps 0..3, g = w) ----
    if (w < GG) {
        const int g = w;
        float* lrow = &sm[OFF_LOGIT + g * SS];
        float lmax = -INFINITY; int lidx = 0x7fffffff;
        #pragma unroll 4
        for (int j = 0; j < 32; j++) {
            float v = lrow[j * 32 + lane];
            if (v > lmax) { lmax = v; lidx = j * 32 + lane; }
        }
        float m0 = 0.f, myv = 0.f; int myi = 0;
        for (int k = 0; k < KK; k++) {
            float bv = lmax; int bi = lidx;
            #pragma unroll
            for (int o = 16; o > 0; o >>= 1) {
                float ov = __shfl_down_sync(0xffffffffu, bv, o);
                int   oi = __shfl_down_sync(0xffffffffu, bi, o);
                if (ov > bv || (ov == bv && oi < bi)) { bv = ov; bi = oi; }
            }
            bv = __shfl_sync(0xffffffffu, bv, 0);
            bi = __shfl_sync(0xffffffffu, bi, 0);
            if (k == 0) m0 = bv;
            if (lane == k) { myv = bv; myi = bi; }
            if ((bi & 31) == lane) {
                lrow[bi] = -INFINITY;
                lmax = -INFINITY; lidx = 0x7fffffff;
                #pragma unroll 4
                for (int j = 0; j < 32; j++) {
                    float v = lrow[j * 32 + lane];
                    if (v > lmax) { lmax = v; lidx = j * 32 + lane; }
                }
            }
        }
        float e = expf(myv - m0);
        float sum = e;
        #pragma unroll
        for (int o = 16; o > 0; o >>= 1) sum += __shfl_xor_sync(0xffffffffu, sum, o);
        float wgt = e / sum;
        sm[OFF_TOPW + g * KK + lane] = wgt;
        ((int*)sm)[OFF_TOPI + g * KK + lane] = myi;
        out_wts[(size_t)(b0 + g) * SS + myi] = wgt;
        g_topw[(size_t)(b0 + g) * KK + lane] = wgt;
        g_topi[(size_t)(b0 + g) * KK + lane] = myi;
    }
    __syncthreads();

    // ---- Phase 6: read[g][d] = sum_k w_k * memory[b][idx_k][d] ----
    {
        const int d  = t & 127;
        const int g0 = t >> 7;
        #pragma unroll
        for (int j = 0; j < 2; j++) {
            int g = g0 + j * 2;
            const float* mrow = memory + (size_t)(b0 + g) * SS * DD;
            float accr = 0.f;
            #pragma unroll 8
            for (int k = 0; k < KK; k++) {
                float wk = sm[OFF_TOPW + g * KK + k];
                int   ik = ((int*)sm)[OFF_TOPI + g * KK + k];
                accr += wk * mrow[(size_t)ik * DD + d];
            }
            sm[OFF_READ + g * DD + d] = accr;
            out_read[(size_t)(b0 + g) * DD + d] = accr;
        }
    }
    __syncthreads();

    // ---- Phase 7: gate (warps 0..3, g = w) ----
    if (w < GG) {
        const int g = w;
        float gr = 0.f, dr = 0.f;
        #pragma unroll
        for (int i = 0; i < 4; i++) {
            float rv = sm[OFF_READ + g * DD + lane * 4 + i];
            gr += rv * wgw[HH + lane * 4 + i];
            dr += rv * dmw[HH + lane * 4 + i];
        }
        #pragma unroll
        for (int o = 16; o > 0; o >>= 1) {
            gr += __shfl_down_sync(0xffffffffu, gr, o);
            dr += __shfl_down_sync(0xffffffffu, dr, o);
        }
        if (lane == 0) {
            float gl = sm[OFF_MISC + g * 8 + 0] + sm[OFF_MISC + g * 8 + 4];
            float dl = sm[OFF_MISC + g * 8 + 1] + sm[OFF_MISC + g * 8 + 5];
            float pl = sm[OFF_MISC + g * 8 + 2] + sm[OFF_MISC + g * 8 + 6];
            float gate = 1.f / (1.f + expf(-(gl + gr + wgb[0])));
            float dmd  = tanhf(dl + dr + dmb[0]);
            gate = gate * (0.75f + 0.25f * (dmd + 1.f));
            gate = fminf(fmaxf(gate, 0.f), 1.f);
            gate *= 0.5f * (1.f + cosf(pl + phb[0]));
            g_gate[b0 + g] = gate;
        }
    }
}

// ---- fixup: rewrite only the B*K modified rows (4 rows per warp) ----
__global__ void __launch_bounds__(256)
amt_fixup(const float* __restrict__ memory, float* __restrict__ out)
{
    const int lane = threadIdx.x & 31, wrp = threadIdx.x >> 5;
    const int W  = blockIdx.x * 8 + wrp;   // 0..4095
    const int r0 = W * 4;
    const int b  = r0 >> 5;
    const int k0 = r0 & 31;

    float gate = g_gate[b];
    const float4* v4 = (const float4*)g_value + (size_t)b * 32;
    float4 v = v4[lane];

    int idx[4]; float gw[4]; float4 m[4];
    const float4* m4 = (const float4*)memory;
    #pragma unroll
    for (int j = 0; j < 4; j++) {
        idx[j] = g_topi[b * KK + k0 + j];
        gw[j]  = gate * g_topw[b * KK + k0 + j];
    }
    #pragma unroll
    for (int j = 0; j < 4; j++)
        m[j] = m4[((size_t)b * SS + idx[j]) * 32 + lane];

    float4* o4 = (float4*)(out + (size_t)BB * DD);
    #pragma unroll
    for (int j = 0; j < 4; j++) {
        float4 r = m[j];
        r.x += gw[j] * (v.x - r.x);
        r.y += gw[j] * (v.y - r.y);
        r.z += gw[j] * (v.z - r.z);
        r.w += gw[j] * (v.w - r.w);
        o4[((size_t)b * SS + idx[j]) * 32 + lane] = r;
    }
}

extern "C" void kernel_launch(void* const* d_in, const int* in_sizes, int n_in,
                              void* d_out, int out_size)
{
    const float* latent = (const float*)d_in[0];
    const float* memory = (const float*)d_in[1];
    const float* rqw    = (const float*)d_in[2];
    const float* rqb    = (const float*)d_in[3];
    const float* mkey   = (const float*)d_in[4];
    const float* wgw    = (const float*)d_in[5];
    const float* wgb    = (const float*)d_in[6];
    const float* dmw    = (const float*)d_in[7];
    const float* dmb    = (const float*)d_in[8];
    const float* phw    = (const float*)d_in[9];
    const float* phb    = (const float*)d_in[10];
    const float* wvw    = (const float*)d_in[11];
    const float* wvb    = (const float*)d_in[12];
    float* out = (float*)d_out;

    cudaFuncSetAttribute(amt_front, cudaFuncAttributeMaxDynamicSharedMemorySize, SMEM_BYTES);

    // Fork: frontend (main stream, launched first so its 128 blocks get SMs
    // immediately) || SM copy kernel (s2, 8192 zero-smem blocks backfill the
    // machine). Join both before fixup.
    cudaEventRecord(g_res.e0, 0);
    cudaStreamWaitEvent(g_res.s2, g_res.e0, 0);

    amt_front<<<NA, TA, SMEM_BYTES>>>(latent, memory, rqw, rqb, mkey,
                                      wgw, wgb, dmw, dmb, phw, phb,
                                      wvw, wvb, out);

    amt_copy<<<NCPY, 256, 0, g_res.s2>>>(memory, out);
    cudaEventRecord(g_res.e1, g_res.s2);

    cudaStreamWaitEvent(0, g_res.e1, 0);
    amt_fixup<<<512, 256>>>(memory, out);
}

// round 6
// speedup vs baseline: 1.5531x; 1.1062x over previous
#include <cuda_runtime.h>
#include <math.h>

#define BB 512
#define HH 1024
#define SS 1024
#define DD 128
#define KK 32
#define GG 4           // batches per frontend block
#define TA 512         // threads in frontend block (16 warps)
#define NA (BB / GG)   // 128 frontend blocks
#define NCPY 8192      // copy blocks: 8192 * 256 threads * 8 float4 = 256MB

// scratch (no allocations allowed)
__device__ float g_gate[BB];
__device__ float g_value[BB * DD];
__device__ float g_topw[BB * KK];
__device__ int   g_topi[BB * KK];

// shared memory layout (float offsets)
#define OFF_Q      0        // 512:   q[4][128]
#define OFF_LOGIT  512      // 4096:  logits[4][1024]
#define OFF_KEY    4608     // 32768: 2 x [4 j][1024 s] float4 planes (16 d per chunk)
#define KEYBUF     16384
#define OFF_PART   37376    // 16896: q-partials [16w][4g][132]
#define OFF_PARTV  45824    // 8448:  v-partials (PART+8448)
#define OFF_TOPW   54272    // 128
#define OFF_TOPI   54400    // 128
#define OFF_READ   54528    // 512
#define OFF_MISC   55040    // 64: [4 g][4 qtr][gate,dmd,phase,_]
#define SMEM_FLOATS 55104
#define SMEM_BYTES (SMEM_FLOATS * 4)   // 220,416 B

__device__ __forceinline__ void cp16(unsigned dst, const void* src) {
    asm volatile("cp.async.cg.shared.global [%0], [%1], 16;" :: "r"(dst), "l"(src));
}
__device__ __forceinline__ void cp_commit() {
    asm volatile("cp.async.commit_group;");
}

// ---- one-time stream/event resources (host-side, created at load) ----
struct AmtRes {
    cudaStream_t s2;
    cudaEvent_t e0, e1;
    AmtRes() {
        int lo, hi;
        cudaDeviceGetStreamPriorityRange(&lo, &hi);
        cudaStreamCreateWithPriority(&s2, cudaStreamNonBlocking, lo);
        cudaEventCreateWithFlags(&e0, cudaEventDisableTiming);
        cudaEventCreateWithFlags(&e1, cudaEventDisableTiming);
    }
};
static AmtRes g_res;

// ---- SM streaming copy: memory -> out.new_memory (256 MB) ----
__global__ void __launch_bounds__(256)
amt_copy(const float* __restrict__ memory, float* __restrict__ out)
{
    const int t = threadIdx.x;
    const size_t base = (size_t)blockIdx.x * 2048 + t;
    const float4* s4 = (const float4*)memory;
    float4* o4 = (float4*)(out + (size_t)BB * DD);
    float4 v[8];
    #pragma unroll
    for (int k = 0; k < 8; k++) v[k] = __ldcs(&s4[base + (size_t)k * 256]);
    #pragma unroll
    for (int k = 0; k < 8; k++) __stcs(&o4[base + (size_t)k * 256], v[k]);
}

__global__ void __launch_bounds__(TA)
amt_front(const float* __restrict__ latent,
          const float* __restrict__ memory,
          const float* __restrict__ rqw,  const float* __restrict__ rqb,
          const float* __restrict__ mkey,
          const float* __restrict__ wgw,  const float* __restrict__ wgb,
          const float* __restrict__ dmw,  const float* __restrict__ dmb,
          const float* __restrict__ phw,  const float* __restrict__ phb,
          const float* __restrict__ wvw,  const float* __restrict__ wvb,
          float* __restrict__ out)
{
    extern __shared__ float sm[];
    const int t    = threadIdx.x;
    const int lane = t & 31;
    const int w    = t >> 5;       // 0..15
    const int b0   = blockIdx.x * GG;
    const unsigned sb = (unsigned)__cvta_generic_to_shared(sm);

    float* out_read = out;                                           // [B][D]
    float* out_wts  = out + (size_t)BB * DD + (size_t)BB * SS * DD;  // [B][S]

    // ---- prefetch mkey chunks 0 and 1 (16 d each) into double buffer ----
    #pragma unroll
    for (int dc = 0; dc < 2; dc++) {
        #pragma unroll
        for (int p = t; p < SS * 4; p += TA) {
            int j = p & 3, s = p >> 2;
            cp16(sb + (OFF_KEY + dc * KEYBUF + (j * SS + s) * 4) * 4,
                 mkey + (size_t)s * DD + dc * 16 + j * 4);
        }
        cp_commit();
    }

    // ---- Phase 0: zero this block's weights rows ----
    {
        float4* p = (float4*)(out_wts + (size_t)b0 * SS);
        #pragma unroll
        for (int i = t; i < GG * SS / 4; i += TA)
            p[i] = make_float4(0.f, 0.f, 0.f, 0.f);
    }

    // ---- Phase 1: latent-side gate/dmd/phase partials; warp w: g=w&3, qtr=w>>2 ----
    {
        const int g = w & 3, qtr = w >> 2;
        const float* lat = latent + (size_t)(b0 + g) * HH + qtr * 256;
        const int off = qtr * 256;
        float gl = 0.f, dl = 0.f, pl = 0.f;
        #pragma unroll
        for (int j = 0; j < 8; j++) {
            int h = j * 32 + lane;
            float lv = lat[h];
            gl += lv * wgw[off + h];
            dl += lv * dmw[off + h];
            pl += lv * phw[off + h];
        }
        #pragma unroll
        for (int o = 16; o > 0; o >>= 1) {
            gl += __shfl_down_sync(0xffffffffu, gl, o);
            dl += __shfl_down_sync(0xffffffffu, dl, o);
            pl += __shfl_down_sync(0xffffffffu, pl, o);
        }
        if (lane == 0) {
            sm[OFF_MISC + g * 16 + qtr * 4 + 0] = gl;
            sm[OFF_MISC + g * 16 + qtr * 4 + 1] = dl;
            sm[OFF_MISC + g * 16 + qtr * 4 + 2] = pl;
        }
    }

    // ---- latent register tile: warp w owns h in [w*64, w*64+64) ----
    float latreg[GG][2];
    #pragma unroll
    for (int g = 0; g < GG; g++)
        #pragma unroll
        for (int k = 0; k < 2; k++)
            latreg[g][k] = latent[(size_t)(b0 + g) * HH + w * 64 + k * 32 + lane];

    // ---- Phase 2+3 fused: query & value GEMMs ----
    {
        const float4* Q4 = (const float4*)rqw;
        const float4* V4 = (const float4*)wvw;
        float4 aq[GG], av[GG];
        #pragma unroll
        for (int g = 0; g < GG; g++) {
            aq[g] = make_float4(0.f, 0.f, 0.f, 0.f);
            av[g] = make_float4(0.f, 0.f, 0.f, 0.f);
        }
        #pragma unroll
        for (int k = 0; k < 2; k++) {
            #pragma unroll 8
            for (int i = 0; i < 32; i++) {
                size_t row = (size_t)(w * 64 + k * 32 + i) * 32 + lane;
                float4 wq = Q4[row];
                float4 wv = V4[row];
                #pragma unroll
                for (int g = 0; g < GG; g++) {
                    float a = __shfl_sync(0xffffffffu, latreg[g][k], i);
                    aq[g].x += a * wq.x; aq[g].y += a * wq.y;
                    aq[g].z += a * wq.z; aq[g].w += a * wq.w;
                    av[g].x += a * wv.x; av[g].y += a * wv.y;
                    av[g].z += a * wv.z; av[g].w += a * wv.w;
                }
            }
        }
        #pragma unroll
        for (int g = 0; g < GG; g++) {
            *(float4*)&sm[OFF_PART  + (w * 4 + g) * 132 + lane * 4] = aq[g];
            *(float4*)&sm[OFF_PARTV + (w * 4 + g) * 132 + lane * 4] = av[g];
        }
    }
    __syncthreads();
    {   // reduce partials: thread -> one (g,d)
        const int g = t >> 7, d = t & 127;
        float sq = rqb[d], sv = wvb[d];
        #pragma unroll
        for (int ww = 0; ww < 16; ww++) {
            sq += sm[OFF_PART  + (ww * 4 + g) * 132 + d];
            sv += sm[OFF_PARTV + (ww * 4 + g) * 132 + d];
        }
        sm[OFF_Q + g * DD + d] = sq;
        g_value[(size_t)(b0 + g) * DD + d] = sv;
    }

    // ---- Phase 4: logits via double-buffered cp.async pipeline, 8 chunks of 16 d ----
    float lac[2][GG];
    #pragma unroll
    for (int u = 0; u < 2; u++)
        #pragma unroll
        for (int g = 0; g < GG; g++) lac[u][g] = 0.f;

    for (int dc = 0; dc < 8; dc++) {
        if (dc < 7) asm volatile("cp.async.wait_group 1;");
        else        asm volatile("cp.async.wait_group 0;");
        __syncthreads();
        const int buf = OFF_KEY + (dc & 1) * KEYBUF;
        #pragma unroll
        for (int j = 0; j < 4; j++) {
            float4 q4[GG];
            #pragma unroll
            for (int g = 0; g < GG; g++)
                q4[g] = *(const float4*)&sm[OFF_Q + g * DD + dc * 16 + j * 4];
            #pragma unroll
            for (int u = 0; u < 2; u++) {
                int s = w * 64 + u * 32 + lane;
                float4 k4 = *(const float4*)&sm[buf + (j * SS + s) * 4];
                #pragma unroll
                for (int g = 0; g < GG; g++)
                    lac[u][g] += k4.x * q4[g].x + k4.y * q4[g].y
                               + k4.z * q4[g].z + k4.w * q4[g].w;
            }
        }
        __syncthreads();
        if (dc < 6) {   // prefetch chunk dc+2 into the buffer just freed
            const int nb = OFF_KEY + (dc & 1) * KEYBUF;
            #pragma unroll
            for (int p = t; p < SS * 4; p += TA) {
                int j = p & 3, s = p >> 2;
                cp16(sb + (nb + (j * SS + s) * 4) * 4,
                     mkey + (size_t)s * DD + (dc + 2) * 16 + j * 4);
            }
            cp_commit();
        }
    }
    #pragma unroll
    for (int u = 0; u < 2; u++) {
        int s = w * 64 + u * 32 + lane;
        #pragma unroll
        for (int g = 0; g < GG; g++)
            sm[OFF_LOGIT + g * SS + s] = lac[u][g];
    }
    __syncthreads();

    // ---- Phase 5: top-32 + renormalized weights (warps 0..3, g = w) ----
    if (w < GG) {
        const int g = w;
        float* lrow = &sm[OFF_LOGIT + g * SS];
        float lmax = -INFINITY; int lidx = 0x7fffffff;
        #pragma unroll 4
        for (int j = 0; j < 32; j++) {
            float v = lrow[j * 32 + lane];
            if (v > lmax) { lmax = v; lidx = j * 32 + lane; }
        }
        float m0 = 0.f, myv = 0.f; int myi = 0;
        for (int k = 0; k < KK; k++) {
            float bv = lmax; int bi = lidx;
            #pragma unroll
            for (int o = 16; o > 0; o >>= 1) {
                float ov = __shfl_down_sync(0xffffffffu, bv, o);
                int   oi = __shfl_down_sync(0xffffffffu, bi, o);
                if (ov > bv || (ov == bv && oi < bi)) { bv = ov; bi = oi; }
            }
            bv = __shfl_sync(0xffffffffu, bv, 0);
            bi = __shfl_sync(0xffffffffu, bi, 0);
            if (k == 0) m0 = bv;
            if (lane == k) { myv = bv; myi = bi; }
            if ((bi & 31) == lane) {
                lrow[bi] = -INFINITY;
                lmax = -INFINITY; lidx = 0x7fffffff;
                #pragma unroll 4
                for (int j = 0; j < 32; j++) {
                    float v = lrow[j * 32 + lane];
                    if (v > lmax) { lmax = v; lidx = j * 32 + lane; }
                }
            }
        }
        float e = expf(myv - m0);
        float sum = e;
        #pragma unroll
        for (int o = 16; o > 0; o >>= 1) sum += __shfl_xor_sync(0xffffffffu, sum, o);
        float wgt = e / sum;
        sm[OFF_TOPW + g * KK + lane] = wgt;
        ((int*)sm)[OFF_TOPI + g * KK + lane] = myi;
        out_wts[(size_t)(b0 + g) * SS + myi] = wgt;
        g_topw[(size_t)(b0 + g) * KK + lane] = wgt;
        g_topi[(size_t)(b0 + g) * KK + lane] = myi;
    }
    __syncthreads();

    // ---- Phase 6: read[g][d] = sum_k w_k * memory[b][idx_k][d]; thread = (g,d) ----
    {
        const int g = t >> 7, d = t & 127;
        const float* mrow = memory + (size_t)(b0 + g) * SS * DD;
        float accr = 0.f;
        #pragma unroll 8
        for (int k = 0; k < KK; k++) {
            float wk = sm[OFF_TOPW + g * KK + k];
            int   ik = ((int*)sm)[OFF_TOPI + g * KK + k];
            accr += wk * mrow[(size_t)ik * DD + d];
        }
        sm[OFF_READ + g * DD + d] = accr;
        out_read[(size_t)(b0 + g) * DD + d] = accr;
    }
    __syncthreads();

    // ---- Phase 7: gate (warps 0..3, g = w) ----
    if (w < GG) {
        const int g = w;
        float gr = 0.f, dr = 0.f;
        #pragma unroll
        for (int i = 0; i < 4; i++) {
            float rv = sm[OFF_READ + g * DD + lane * 4 + i];
            gr += rv * wgw[HH + lane * 4 + i];
            dr += rv * dmw[HH + lane * 4 + i];
        }
        #pragma unroll
        for (int o = 16; o > 0; o >>= 1) {
            gr += __shfl_down_sync(0xffffffffu, gr, o);
            dr += __shfl_down_sync(0xffffffffu, dr, o);
        }
        if (lane == 0) {
            float gl = 0.f, dl = 0.f, pl = 0.f;
            #pragma unroll
            for (int qtr = 0; qtr < 4; qtr++) {
                gl += sm[OFF_MISC + g * 16 + qtr * 4 + 0];
                dl += sm[OFF_MISC + g * 16 + qtr * 4 + 1];
                pl += sm[OFF_MISC + g * 16 + qtr * 4 + 2];
            }
            float gate = 1.f / (1.f + expf(-(gl + gr + wgb[0])));
            float dmd  = tanhf(dl + dr + dmb[0]);
            gate = gate * (0.75f + 0.25f * (dmd + 1.f));
            gate = fminf(fmaxf(gate, 0.f), 1.f);
            gate *= 0.5f * (1.f + cosf(pl + phb[0]));
            g_gate[b0 + g] = gate;
        }
    }
}

// ---- fixup: rewrite only the B*K modified rows (8 rows per warp) ----
__global__ void __launch_bounds__(256)
amt_fixup(const float* __restrict__ memory, float* __restrict__ out)
{
    const int lane = threadIdx.x & 31, wrp = threadIdx.x >> 5;
    const int W  = blockIdx.x * 8 + wrp;   // 0..2047
    const int r0 = W * 8;
    const int b  = r0 >> 5;
    const int k0 = r0 & 31;

    float gate = g_gate[b];
    const float4* v4 = (const float4*)g_value + (size_t)b * 32;
    float4 v = v4[lane];

    int idx[8]; float gw[8]; float4 m[8];
    const float4* m4 = (const float4*)memory;
    #pragma unroll
    for (int j = 0; j < 8; j++) {
        idx[j] = g_topi[b * KK + k0 + j];
        gw[j]  = gate * g_topw[b * KK + k0 + j];
    }
    #pragma unroll
    for (int j = 0; j < 8; j++)
        m[j] = m4[((size_t)b * SS + idx[j]) * 32 + lane];

    float4* o4 = (float4*)(out + (size_t)BB * DD);
    #pragma unroll
    for (int j = 0; j < 8; j++) {
        float4 r = m[j];
        r.x += gw[j] * (v.x - r.x);
        r.y += gw[j] * (v.y - r.y);
        r.z += gw[j] * (v.z - r.z);
        r.w += gw[j] * (v.w - r.w);
        o4[((size_t)b * SS + idx[j]) * 32 + lane] = r;
    }
}

extern "C" void kernel_launch(void* const* d_in, const int* in_sizes, int n_in,
                              void* d_out, int out_size)
{
    const float* latent = (const float*)d_in[0];
    const float* memory = (const float*)d_in[1];
    const float* rqw    = (const float*)d_in[2];
    const float* rqb    = (const float*)d_in[3];
    const float* mkey   = (const float*)d_in[4];
    const float* wgw    = (const float*)d_in[5];
    const float* wgb    = (const float*)d_in[6];
    const float* dmw    = (const float*)d_in[7];
    const float* dmb    = (const float*)d_in[8];
    const float* phw    = (const float*)d_in[9];
    const float* phb    = (const float*)d_in[10];
    const float* wvw    = (const float*)d_in[11];
    const float* wvb    = (const float*)d_in[12];
    float* out = (float*)d_out;

    cudaFuncSetAttribute(amt_front, cudaFuncAttributeMaxDynamicSharedMemorySize, SMEM_BYTES);

    // Fork: frontend (main stream) || SM copy (s2, low prio, backfills SMs).
    cudaEventRecord(g_res.e0, 0);
    cudaStreamWaitEvent(g_res.s2, g_res.e0, 0);

    amt_front<<<NA, TA, SMEM_BYTES>>>(latent, memory, rqw, rqb, mkey,
                                      wgw, wgb, dmw, dmb, phw, phb,
                                      wvw, wvb, out);

    amt_copy<<<NCPY, 256, 0, g_res.s2>>>(memory, out);
    cudaEventRecord(g_res.e1, g_res.s2);

    cudaStreamWaitEvent(0, g_res.e1, 0);
    amt_fixup<<<256, 256>>>(memory, out);
}

// round 7
// speedup vs baseline: 1.5959x; 1.0275x over previous
#include <cuda_runtime.h>
#include <math.h>

#define BB 512
#define HH 1024
#define SS 1024
#define DD 128
#define KK 32
#define GG 4           // batches per frontend block
#define TA 512         // threads in frontend block (16 warps)
#define NA (BB / GG)   // 128 frontend blocks

// copy split: SM blocks copy the head, CE memcpy the tail.
// total new_memory = 16,777,216 float4 (256 MB)
#define SMCPY_BLOCKS 5376                     // 5376*2048 = 11,010,048 float4 (168 MB)
#define SMCPY_F4     ((size_t)SMCPY_BLOCKS * 2048)
#define TOTAL_F4     ((size_t)BB * SS * DD / 4)
#define CE_F4        (TOTAL_F4 - SMCPY_F4)    // 5,767,168 float4 (88 MB)

// scratch (no allocations allowed)
__device__ float g_gate[BB];
__device__ float g_value[BB * DD];
__device__ float g_topw[BB * KK];
__device__ int   g_topi[BB * KK];

// shared memory layout (float offsets)
#define OFF_Q      0        // 512:   q[4][128]
#define OFF_LOGIT  512      // 4096:  logits[4][1024]  (aliased as s_lat during GEMM)
#define OFF_KEY    4608     // 32768: 2 x [4 j][1024 s] float4 planes (16 d per chunk)
#define KEYBUF     16384
#define OFF_PART   37376    // 8448: q-partials [16w][4g][132]
#define OFF_PARTV  45824    // 8448: v-partials
#define OFF_TOPW   54272    // 128
#define OFF_TOPI   54400    // 128
#define OFF_READ   54528    // 512
#define OFF_MISC   55040    // 64: [4 g][4 qtr][gate,dmd,phase,_]
#define SMEM_FLOATS 55104
#define SMEM_BYTES (SMEM_FLOATS * 4)   // 220,416 B

__device__ __forceinline__ void cp16(unsigned dst, const void* src) {
    asm volatile("cp.async.cg.shared.global [%0], [%1], 16;" :: "r"(dst), "l"(src));
}
__device__ __forceinline__ void cp_commit() {
    asm volatile("cp.async.commit_group;");
}

// ---- one-time stream/event resources (host-side, created at load) ----
struct AmtRes {
    cudaStream_t s2, s3;
    cudaEvent_t e0, e1, e2;
    AmtRes() {
        int lo, hi;
        cudaDeviceGetStreamPriorityRange(&lo, &hi);
        cudaStreamCreateWithPriority(&s2, cudaStreamNonBlocking, lo);
        cudaStreamCreateWithPriority(&s3, cudaStreamNonBlocking, lo);
        cudaEventCreateWithFlags(&e0, cudaEventDisableTiming);
        cudaEventCreateWithFlags(&e1, cudaEventDisableTiming);
        cudaEventCreateWithFlags(&e2, cudaEventDisableTiming);
    }
};
static AmtRes g_res;

// ---- SM streaming copy: head SMCPY_F4 float4 of memory -> out.new_memory ----
__global__ void __launch_bounds__(256)
amt_copy(const float* __restrict__ memory, float* __restrict__ out)
{
    const int t = threadIdx.x;
    const size_t base = (size_t)blockIdx.x * 2048 + t;
    const float4* s4 = (const float4*)memory;
    float4* o4 = (float4*)(out + (size_t)BB * DD);
    float4 v[8];
    #pragma unroll
    for (int k = 0; k < 8; k++) v[k] = __ldcs(&s4[base + (size_t)k * 256]);
    #pragma unroll
    for (int k = 0; k < 8; k++) __stcs(&o4[base + (size_t)k * 256], v[k]);
}

__global__ void __launch_bounds__(TA)
amt_front(const float* __restrict__ latent,
          const float* __restrict__ memory,
          const float* __restrict__ rqw,  const float* __restrict__ rqb,
          const float* __restrict__ mkey,
          const float* __restrict__ wgw,  const float* __restrict__ wgb,
          const float* __restrict__ dmw,  const float* __restrict__ dmb,
          const float* __restrict__ phw,  const float* __restrict__ phb,
          const float* __restrict__ wvw,  const float* __restrict__ wvb,
          float* __restrict__ out)
{
    extern __shared__ float sm[];
    const int t    = threadIdx.x;
    const int lane = t & 31;
    const int w    = t >> 5;       // 0..15
    const int b0   = blockIdx.x * GG;
    const unsigned sb = (unsigned)__cvta_generic_to_shared(sm);

    float* out_read = out;                                           // [B][D]
    float* out_wts  = out + (size_t)BB * DD + (size_t)BB * SS * DD;  // [B][S]
    float* s_lat = &sm[OFF_LOGIT];   // [4 g][1024 h], aliases logits region

    // ---- prefetch mkey chunks 0 and 1 (16 d each) into double buffer ----
    #pragma unroll
    for (int dc = 0; dc < 2; dc++) {
        #pragma unroll
        for (int p = t; p < SS * 4; p += TA) {
            int j = p & 3, s = p >> 2;
            cp16(sb + (OFF_KEY + dc * KEYBUF + (j * SS + s) * 4) * 4,
                 mkey + (size_t)s * DD + dc * 16 + j * 4);
        }
        cp_commit();
    }

    // ---- stage latent tile [4][1024] into smem ----
    {
        const float4* lat4 = (const float4*)(latent + (size_t)b0 * HH);
        float4* sl4 = (float4*)s_lat;
        #pragma unroll
        for (int i = 0; i < 2; i++) {
            int p = t + i * TA;          // 0..1023
            sl4[p] = lat4[p];
        }
    }

    // ---- Phase 0: zero this block's weights rows ----
    {
        float4* p = (float4*)(out_wts + (size_t)b0 * SS);
        #pragma unroll
        for (int i = t; i < GG * SS / 4; i += TA)
            p[i] = make_float4(0.f, 0.f, 0.f, 0.f);
    }
    __syncthreads();   // s_lat visible

    // ---- Phase 1: latent-side gate/dmd/phase partials; warp w: g=w&3, qtr=w>>2 ----
    {
        const int g = w & 3, qtr = w >> 2;
        const int off = qtr * 256;
        float gl = 0.f, dl = 0.f, pl = 0.f;
        #pragma unroll
        for (int j = 0; j < 8; j++) {
            int h = off + j * 32 + lane;
            float lv = s_lat[g * HH + h];
            gl += lv * wgw[h];
            dl += lv * dmw[h];
            pl += lv * phw[h];
        }
        #pragma unroll
        for (int o = 16; o > 0; o >>= 1) {
            gl += __shfl_down_sync(0xffffffffu, gl, o);
            dl += __shfl_down_sync(0xffffffffu, dl, o);
            pl += __shfl_down_sync(0xffffffffu, pl, o);
        }
        if (lane == 0) {
            sm[OFF_MISC + g * 16 + qtr * 4 + 0] = gl;
            sm[OFF_MISC + g * 16 + qtr * 4 + 1] = dl;
            sm[OFF_MISC + g * 16 + qtr * 4 + 2] = pl;
        }
    }

    // ---- Phase 2+3 fused: query & value GEMMs (latent via LDS broadcast) ----
    {
        const float4* Q4 = (const float4*)rqw;
        const float4* V4 = (const float4*)wvw;
        float4 aq[GG], av[GG];
        #pragma unroll
        for (int g = 0; g < GG; g++) {
            aq[g] = make_float4(0.f, 0.f, 0.f, 0.f);
            av[g] = make_float4(0.f, 0.f, 0.f, 0.f);
        }
        const int hb = w * 64;
        #pragma unroll
        for (int k = 0; k < 2; k++) {
            #pragma unroll 8
            for (int i = 0; i < 32; i++) {
                int h = hb + k * 32 + i;
                size_t row = (size_t)h * 32 + lane;
                float4 wq = Q4[row];
                float4 wv = V4[row];
                #pragma unroll
                for (int g = 0; g < GG; g++) {
                    float a = s_lat[g * HH + h];   // same-address LDS broadcast
                    aq[g].x += a * wq.x; aq[g].y += a * wq.y;
                    aq[g].z += a * wq.z; aq[g].w += a * wq.w;
                    av[g].x += a * wv.x; av[g].y += a * wv.y;
                    av[g].z += a * wv.z; av[g].w += a * wv.w;
                }
            }
        }
        #pragma unroll
        for (int g = 0; g < GG; g++) {
            *(float4*)&sm[OFF_PART  + (w * 4 + g) * 132 + lane * 4] = aq[g];
            *(float4*)&sm[OFF_PARTV + (w * 4 + g) * 132 + lane * 4] = av[g];
        }
    }
    __syncthreads();
    {   // reduce partials: thread -> one (g,d)
        const int g = t >> 7, d = t & 127;
        float sq = rqb[d], sv = wvb[d];
        #pragma unroll
        for (int ww = 0; ww < 16; ww++) {
            sq += sm[OFF_PART  + (ww * 4 + g) * 132 + d];
            sv += sm[OFF_PARTV + (ww * 4 + g) * 132 + d];
        }
        sm[OFF_Q + g * DD + d] = sq;
        g_value[(size_t)(b0 + g) * DD + d] = sv;
    }

    // ---- Phase 4: logits via double-buffered cp.async pipeline, 8 chunks of 16 d ----
    float lac[2][GG];
    #pragma unroll
    for (int u = 0; u < 2; u++)
        #pragma unroll
        for (int g = 0; g < GG; g++) lac[u][g] = 0.f;

    for (int dc = 0; dc < 8; dc++) {
        if (dc < 7) asm volatile("cp.async.wait_group 1;");
        else        asm volatile("cp.async.wait_group 0;");
        __syncthreads();
        const int buf = OFF_KEY + (dc & 1) * KEYBUF;
        #pragma unroll
        for (int j = 0; j < 4; j++) {
            float4 q4[GG];
            #pragma unroll
            for (int g = 0; g < GG; g++)
                q4[g] = *(const float4*)&sm[OFF_Q + g * DD + dc * 16 + j * 4];
            #pragma unroll
            for (int u = 0; u < 2; u++) {
                int s = w * 64 + u * 32 + lane;
                float4 k4 = *(const float4*)&sm[buf + (j * SS + s) * 4];
                #pragma unroll
                for (int g = 0; g < GG; g++)
                    lac[u][g] += k4.x * q4[g].x + k4.y * q4[g].y
                               + k4.z * q4[g].z + k4.w * q4[g].w;
            }
        }
        __syncthreads();
        if (dc < 6) {   // prefetch chunk dc+2 into the buffer just freed
            const int nb = OFF_KEY + (dc & 1) * KEYBUF;
            #pragma unroll
            for (int p = t; p < SS * 4; p += TA) {
                int j = p & 3, s = p >> 2;
                cp16(sb + (nb + (j * SS + s) * 4) * 4,
                     mkey + (size_t)s * DD + (dc + 2) * 16 + j * 4);
            }
            cp_commit();
        }
    }
    // s_lat dead from here; region becomes logits
    #pragma unroll
    for (int u = 0; u < 2; u++) {
        int s = w * 64 + u * 32 + lane;
        #pragma unroll
        for (int g = 0; g < GG; g++)
            sm[OFF_LOGIT + g * SS + s] = lac[u][g];
    }
    __syncthreads();

    // ---- Phase 5: top-32 + renormalized weights (warps 0..3, g = w) ----
    if (w < GG) {
        const int g = w;
        float* lrow = &sm[OFF_LOGIT + g * SS];
        float lmax = -INFINITY; int lidx = 0x7fffffff;
        #pragma unroll 4
        for (int j = 0; j < 32; j++) {
            float v = lrow[j * 32 + lane];
            if (v > lmax) { lmax = v; lidx = j * 32 + lane; }
        }
        float m0 = 0.f, myv = 0.f; int myi = 0;
        for (int k = 0; k < KK; k++) {
            float bv = lmax; int bi = lidx;
            #pragma unroll
            for (int o = 16; o > 0; o >>= 1) {
                float ov = __shfl_down_sync(0xffffffffu, bv, o);
                int   oi = __shfl_down_sync(0xffffffffu, bi, o);
                if (ov > bv || (ov == bv && oi < bi)) { bv = ov; bi = oi; }
            }
            bv = __shfl_sync(0xffffffffu, bv, 0);
            bi = __shfl_sync(0xffffffffu, bi, 0);
            if (k == 0) m0 = bv;
            if (lane == k) { myv = bv; myi = bi; }
            if ((bi & 31) == lane) {
                lrow[bi] = -INFINITY;
                lmax = -INFINITY; lidx = 0x7fffffff;
                #pragma unroll 4
                for (int j = 0; j < 32; j++) {
                    float v = lrow[j * 32 + lane];
                    if (v > lmax) { lmax = v; lidx = j * 32 + lane; }
                }
            }
        }
        float e = expf(myv - m0);
        float sum = e;
        #pragma unroll
        for (int o = 16; o > 0; o >>= 1) sum += __shfl_xor_sync(0xffffffffu, sum, o);
        float wgt = e / sum;
        sm[OFF_TOPW + g * KK + lane] = wgt;
        ((int*)sm)[OFF_TOPI + g * KK + lane] = myi;
        out_wts[(size_t)(b0 + g) * SS + myi] = wgt;
        g_topw[(size_t)(b0 + g) * KK + lane] = wgt;
        g_topi[(size_t)(b0 + g) * KK + lane] = myi;
    }
    __syncthreads();

    // ---- Phase 6: read[g][d] = sum_k w_k * memory[b][idx_k][d]; thread = (g,d) ----
    {
        const int g = t >> 7, d = t & 127;
        const float* mrow = memory + (size_t)(b0 + g) * SS * DD;
        float accr = 0.f;
        #pragma unroll 8
        for (int k = 0; k < KK; k++) {
            float wk = sm[OFF_TOPW + g * KK + k];
            int   ik = ((int*)sm)[OFF_TOPI + g * KK + k];
            accr += wk * mrow[(size_t)ik * DD + d];
        }
        sm[OFF_READ + g * DD + d] = accr;
        out_read[(size_t)(b0 + g) * DD + d] = accr;
    }
    __syncthreads();

    // ---- Phase 7: gate (warps 0..3, g = w) ----
    if (w < GG) {
        const int g = w;
        float gr = 0.f, dr = 0.f;
        #pragma unroll
        for (int i = 0; i < 4; i++) {
            float rv = sm[OFF_READ + g * DD + lane * 4 + i];
            gr += rv * wgw[HH + lane * 4 + i];
            dr += rv * dmw[HH + lane * 4 + i];
        }
        #pragma unroll
        for (int o = 16; o > 0; o >>= 1) {
            gr += __shfl_down_sync(0xffffffffu, gr, o);
            dr += __shfl_down_sync(0xffffffffu, dr, o);
        }
        if (lane == 0) {
            float gl = 0.f, dl = 0.f, pl = 0.f;
            #pragma unroll
            for (int qtr = 0; qtr < 4; qtr++) {
                gl += sm[OFF_MISC + g * 16 + qtr * 4 + 0];
                dl += sm[OFF_MISC + g * 16 + qtr * 4 + 1];
                pl += sm[OFF_MISC + g * 16 + qtr * 4 + 2];
            }
            float gate = 1.f / (1.f + expf(-(gl + gr + wgb[0])));
            float dmd  = tanhf(dl + dr + dmb[0]);
            gate = gate * (0.75f + 0.25f * (dmd + 1.f));
            gate = fminf(fmaxf(gate, 0.f), 1.f);
            gate *= 0.5f * (1.f + cosf(pl + phb[0]));
            g_gate[b0 + g] = gate;
        }
    }
}

// ---- fixup: rewrite only the B*K modified rows (8 rows per warp) ----
__global__ void __launch_bounds__(256)
amt_fixup(const float* __restrict__ memory, float* __restrict__ out)
{
    const int lane = threadIdx.x & 31, wrp = threadIdx.x >> 5;
    const int W  = blockIdx.x * 8 + wrp;   // 0..2047
    const int r0 = W * 8;
    const int b  = r0 >> 5;
    const int k0 = r0 & 31;

    float gate = g_gate[b];
    const float4* v4 = (const float4*)g_value + (size_t)b * 32;
    float4 v = v4[lane];

    int idx[8]; float gw[8]; float4 m[8];
    const float4* m4 = (const float4*)memory;
    #pragma unroll
    for (int j = 0; j < 8; j++) {
        idx[j] = g_topi[b * KK + k0 + j];
        gw[j]  = gate * g_topw[b * KK + k0 + j];
    }
    #pragma unroll
    for (int j = 0; j < 8; j++)
        m[j] = m4[((size_t)b * SS + idx[j]) * 32 + lane];

    float4* o4 = (float4*)(out + (size_t)BB * DD);
    #pragma unroll
    for (int j = 0; j < 8; j++) {
        float4 r = m[j];
        r.x += gw[j] * (v.x - r.x);
        r.y += gw[j] * (v.y - r.y);
        r.z += gw[j] * (v.z - r.z);
        r.w += gw[j] * (v.w - r.w);
        o4[((size_t)b * SS + idx[j]) * 32 + lane] = r;
    }
}

extern "C" void kernel_launch(void* const* d_in, const int* in_sizes, int n_in,
                              void* d_out, int out_size)
{
    const float* latent = (const float*)d_in[0];
    const float* memory = (const float*)d_in[1];
    const float* rqw    = (const float*)d_in[2];
    const float* rqb    = (const float*)d_in[3];
    const float* mkey   = (const float*)d_in[4];
    const float* wgw    = (const float*)d_in[5];
    const float* wgb    = (const float*)d_in[6];
    const float* dmw    = (const float*)d_in[7];
    const float* dmb    = (const float*)d_in[8];
    const float* phw    = (const float*)d_in[9];
    const float* phb    = (const float*)d_in[10];
    const float* wvw    = (const float*)d_in[11];
    const float* wvb    = (const float*)d_in[12];
    float* out = (float*)d_out;

    cudaFuncSetAttribute(amt_front, cudaFuncAttributeMaxDynamicSharedMemorySize, SMEM_BYTES);

    // Fork: frontend (main) || SM copy head (s3) || CE memcpy tail (s2).
    cudaEventRecord(g_res.e0, 0);
    cudaStreamWaitEvent(g_res.s2, g_res.e0, 0);
    cudaStreamWaitEvent(g_res.s3, g_res.e0, 0);

    amt_front<<<NA, TA, SMEM_BYTES>>>(latent, memory, rqw, rqb, mkey,
                                      wgw, wgb, dmw, dmb, phw, phb,
                                      wvw, wvb, out);

    amt_copy<<<SMCPY_BLOCKS, 256, 0, g_res.s3>>>(memory, out);
    cudaEventRecord(g_res.e2, g_res.s3);

    cudaMemcpyAsync(out + (size_t)BB * DD + SMCPY_F4 * 4,
                    memory + SMCPY_F4 * 4,
                    CE_F4 * 16, cudaMemcpyDeviceToDevice, g_res.s2);
    cudaEventRecord(g_res.e1, g_res.s2);

    cudaStreamWaitEvent(0, g_res.e1, 0);
    cudaStreamWaitEvent(0, g_res.e2, 0);
    amt_fixup<<<256, 256>>>(memory, out);
}